// round 8
// baseline (speedup 1.0000x reference)
#include <cuda_runtime.h>
#include <cstdint>

// WKV (RWKV v4) — segmented scan, decoupled lookback, smem-resident segment.
//
//   state_t = lam*state_{t-1} + e^{k_t}(v_t, 1),  lam = exp(-exp(td[c]))
//   y_t = (A_{t-1} + e^u e^{k_t} v_t) / (B_{t-1} + e^u e^{k_t})
//
// Segment (64 steps x 128 ch) lives ENTIRELY in 64KB smem:
//   sweep 1: stream k/v in with an all-upfront cp.async pipeline (8 tiles,
//            8 commit groups, wait_group(7-t) as we scan), compute local
//            (A,B), and overwrite k with e^k in place.
//   sweep 2: re-read e^k / v from smem only — zero global traffic, no EX2.
// 64KB/block -> 3 blocks/SM -> GRID=444 = ONE wave; blocks loop over work
// items in ascending id. Lookback waits only on strictly-lower ids ->
// forward progress by induction (CUB decoupled-lookback argument).
// DRAM traffic = minimum: k+v read once, y written once (.cs stores).
//
// Flags self-clean (slot j has S-1-j consumers; last consumer resets), so
// all device state is zero at kernel end -> graph-replay safe.

constexpr int CH   = 128;            // channels per block == threads
constexpr int SEG  = 64;             // timesteps per segment (smem-resident)
constexpr int TT   = 8;              // rows per cp.async tile
constexpr int NT   = SEG / TT;       // 8 tiles = 8 commit groups
constexpr int S_MAX = 16;            // max segments (SEG*S_MAX >= T_max)
constexpr int GRID  = 444;           // 3 blocks/SM * 148 SMs = one wave
constexpr int SMEM_BYTES = 2 * SEG * CH * (int)sizeof(float); // 64 KB

__device__ float    g_A[1 << 18];
__device__ float    g_B[1 << 18];
__device__ unsigned g_flag[4096];
__device__ unsigned g_cnt[4096];

__device__ __forceinline__ void cpasync16(float* s, const float* g) {
    unsigned sa = (unsigned)__cvta_generic_to_shared(s);
    asm volatile("cp.async.cg.shared.global [%0], [%1], 16;\n"
                 :: "r"(sa), "l"(g) : "memory");
}

__device__ __forceinline__ void stcs(float* p, float v) {
    asm volatile("st.global.cs.f32 [%0], %1;\n" :: "l"(p), "f"(v) : "memory");
}

__device__ __forceinline__ unsigned ld_flag(const unsigned* p) {
    unsigned v;
    asm volatile("ld.global.cg.b32 %0, [%1];\n" : "=r"(v) : "l"(p) : "memory");
    return v;
}

template <int N>
__device__ __forceinline__ void cp_wait() {
    asm volatile("cp.async.wait_group %0;\n" :: "n"(N));
}

__device__ __forceinline__ void cp_wait_dyn(int t) {
    // t = tile index just about to be consumed; groups 0..t must be done.
    switch (t) {
        case 0: cp_wait<NT - 1>(); break;
        case 1: cp_wait<NT - 2>(); break;
        case 2: cp_wait<NT - 3>(); break;
        case 3: cp_wait<NT - 4>(); break;
        case 4: cp_wait<NT - 5>(); break;
        case 5: cp_wait<NT - 6>(); break;
        case 6: cp_wait<NT - 7>(); break;
        default: cp_wait<0>(); break;
    }
}

__device__ __forceinline__ int read_dim(const void* p) {
    int i = *reinterpret_cast<const int*>(p);
    if (i >= 1 && i <= (1 << 20)) return i;
    float f = *reinterpret_cast<const float*>(p);
    int fi = (int)f;
    return (fi >= 1) ? fi : 1;
}

__global__ __launch_bounds__(CH, 3)
void wkv_kernel(const void* __restrict__ seqlen_p,
                const float* __restrict__ td,
                const float* __restrict__ tf,
                const float* __restrict__ kg,
                const float* __restrict__ vg,
                float* __restrict__ out,
                int C, long long BTC)
{
    extern __shared__ float smem[];
    float* sk = smem;             // k, overwritten by e^k during sweep 1
    float* sv = smem + SEG * CH;  // v
    const int tid  = threadIdx.x;
    const int lane = tid & 31;

    const int T = read_dim(seqlen_p);
    const long long BT = BTC / C;
    const int B = (int)(BT / T);
    const int ctiles = (C + CH - 1) / CH;
    const int nrows  = B * ctiles;
    int S_eff = (T + SEG - 1) / SEG;           // seglen <= SEG always
    if (S_eff < 1) S_eff = 1;
    if (S_eff > S_MAX) S_eff = S_MAX;
    const int seglen = (T + S_eff - 1) / S_eff;
    const int nwork  = nrows * S_eff;
    const bool vec_ok = ((C & 3) == 0) &&
                        ((((uintptr_t)kg) & 15) == 0) &&
                        ((((uintptr_t)vg) & 15) == 0);

    for (int w = blockIdx.x; w < nwork; w += gridDim.x) {
        __syncthreads();   // smem reuse across items

        const int s     = w % S_eff;
        const int rowid = w / S_eff;
        const int b     = rowid / ctiles;
        const int c0    = (rowid % ctiles) * CH;
        const int c     = c0 + tid;
        const bool valid = (c < C);

        const int segstart = min(s * seglen, T);
        const int segend   = min(T, segstart + seglen);
        if (segstart >= segend) continue;
        const int len    = segend - segstart;
        const int ntiles = (len + TT - 1) / TT;

        const float* kbase = kg + (long long)b * T * C;
        const float* vbase = vg + (long long)b * T * C;
        float* obase = out + (long long)b * T * C + c;

        // ---- issue ALL tile loads upfront (max MLP), 1 commit per tile ----
        if (vec_ok) {
            for (int t = 0; t < NT; ++t) {
                if (t < ntiles) {
                    const int t0 = segstart + t * TT;
                    #pragma unroll
                    for (int j = 0; j < TT / 4; ++j) {
                        const int q    = tid + j * CH;
                        const int row  = q >> 5;
                        const int col4 = (q & 31) * 4;
                        int gt = t0 + row; if (gt >= segend) gt = segend - 1;
                        const int gc = c0 + col4;
                        if (gc + 4 <= C) {
                            const long long go = (long long)gt * C + gc;
                            cpasync16(sk + (t * TT + row) * CH + col4, kbase + go);
                            cpasync16(sv + (t * TT + row) * CH + col4, vbase + go);
                        }
                    }
                }
                asm volatile("cp.async.commit_group;\n" ::);
            }
        } else {
            for (int r = 0; r < len; ++r) {
                if (valid) {
                    const long long go = (long long)(segstart + r) * C + c;
                    sk[r * CH + tid] = kbase[go];
                    sv[r * CH + tid] = vbase[go];
                }
            }
            __syncthreads();
        }

        const float ew  = valid ? __expf(td[c]) : 0.f;   // e^{td}
        const float lam = __expf(-ew);                   // exp(-e^{td})
        const float eu  = valid ? __expf(tf[c]) : 0.f;

        float A = 0.f, Bs = 0.f;

        // ---- sweep 1: scan tiles as they land; cache e^k in place ----
        // s==0 needs no seed: emit y directly here (single sweep).
        for (int t = 0; t < ntiles; ++t) {
            if (vec_ok) { cp_wait_dyn(t); __syncthreads(); }
            const int base = t * TT;
            const int jmax = min(TT, len - base);
            #pragma unroll
            for (int j = 0; j < TT; ++j) {
                if (j < jmax) {
                    const int idx = (base + j) * CH + tid;
                    const float kt = sk[idx];
                    const float vt = sv[idx];
                    const float ek = __expf(kt);
                    if (s == 0) {
                        const float eku = eu * ek;
                        const float y = __fdividef(fmaf(eku, vt, A), Bs + eku);
                        if (valid)
                            stcs(obase + (long long)(segstart + base + j) * C, y);
                    } else {
                        sk[idx] = ek;       // sweep 2 reads e^k, no recompute
                    }
                    A  = fmaf(lam, A,  ek * vt);
                    Bs = fmaf(lam, Bs, ek);
                }
            }
        }

        // ---- publish local state (only if someone will consume it) ----
        if (s < S_eff - 1) {
            const size_t st = (size_t)w * CH + tid;
            __stcg(&g_A[st], A);
            __stcg(&g_B[st], Bs);
            __threadfence();
            __syncthreads();
            if (tid == 0) atomicExch(&g_flag[w], 1u);
        }
        if (s == 0) continue;

        // ---- lookback: warp-level wait, then fold predecessor locals ----
        if (lane == 0) {
            for (int j = 0; j < s; ++j) {
                const unsigned* f = &g_flag[rowid * S_eff + j];
                while (ld_flag(f) == 0u) __nanosleep(64);
            }
        }
        __syncwarp();

        float sa = 0.f, sb = 0.f;
        #pragma unroll 4
        for (int j = 0; j < s; ++j) {
            int Lj = T - j * seglen;
            Lj = max(0, min(seglen, Lj));
            const float fdec = __expf(-(float)Lj * ew);  // lam^{L_j}
            const size_t st = (size_t)(rowid * S_eff + j) * CH + tid;
            sa = fmaf(fdec, sa, __ldcg(&g_A[st]));
            sb = fmaf(fdec, sb, __ldcg(&g_B[st]));
        }

        // ---- sweep 2: pure-smem seeded re-scan, emit y ----
        A = sa; Bs = sb;
        for (int r = 0; r < len; ++r) {
            const int idx = r * CH + tid;
            const float ek = sk[idx];     // cached e^k
            const float vt = sv[idx];
            const float eku = eu * ek;
            const float y = __fdividef(fmaf(eku, vt, A), Bs + eku);
            if (valid)
                stcs(obase + (long long)(segstart + r) * C, y);
            A  = fmaf(lam, A,  ek * vt);
            Bs = fmaf(lam, Bs, ek);
        }

        // ---- retire consumed flags (off critical path): last consumer of
        // slot j clears it so the next graph replay starts all-zero. ----
        if (tid == 0) {
            for (int j = 0; j < s; ++j) {
                const int wj = rowid * S_eff + j;
                const unsigned need = (unsigned)(S_eff - 1 - j);
                const unsigned got = atomicAdd(&g_cnt[wj], 1u) + 1u;
                if (got == need) {
                    g_cnt[wj] = 0u;
                    atomicExch(&g_flag[wj], 0u);
                }
            }
        }
    }
}

extern "C" void kernel_launch(void* const* d_in, const int* in_sizes, int n_in,
                              void* d_out, int out_size)
{
    // metadata order: batch_size, seq_len, embedding_dim, time_decay,
    //                 time_first, k, v
    const void*  seqlen_p = d_in[1];
    const float* td = (const float*)d_in[3];
    const float* tf = (const float*)d_in[4];
    const float* k  = (const float*)d_in[5];
    const float* v  = (const float*)d_in[6];
    float* out = (float*)d_out;

    const int C = in_sizes[3];
    const long long BTC = in_sizes[5];

    static bool attr_done = false;
    if (!attr_done) {
        cudaFuncSetAttribute(wkv_kernel,
                             cudaFuncAttributeMaxDynamicSharedMemorySize,
                             SMEM_BYTES);
        attr_done = true;
    }

    wkv_kernel<<<GRID, CH, SMEM_BYTES>>>(seqlen_p, td, tf, k, v, out, C, BTC);
}

// round 10
// speedup vs baseline: 1.6755x; 1.6755x over previous
#include <cuda_runtime.h>
#include <cstdint>

// WKV (RWKV v4) — segmented scan + decoupled lookback.
// R4 config (GRID=1024, S=8, proven 5.3 TB/s load continuity) + R7 sync
// improvements. No L2 policy PTX (createpolicy/cache_hint crashed in R9).
//
//   state_t = lam*state_{t-1} + e^{k_t}(v_t, 1),  lam = exp(-exp(td[c]))
//   y_t = (A_{t-1} + e^u e^{k_t} v_t) / (B_{t-1} + e^u e^{k_t})
//
// One work item per block; all 1024 blocks resident (8/SM).
//  - segment 0 emits directly in sweep 1 (no lookback, no re-read)
//  - warp-level lookback wait (lane0 polls all flags, no __syncthreads)
//  - consumer-retire atomics after sweep 2 (off critical path)
//  - sweep-2 cp.async prologue issued before the lookback wait (overlap)
//  - y stores .cs (evict-first)
// Flags self-clean (slot j has S-1-j consumers; last consumer resets) so all
// device state is zero at kernel end -> graph-replay safe, no zeroing pass.

constexpr int CH    = 128;  // channels per block == threads
constexpr int TT    = 8;    // timesteps per smem tile
constexpr int NBUF  = 3;    // cp.async pipeline depth
constexpr int S_MAX = 8;    // max T segments
constexpr int GRID  = 1024;
constexpr int SMEM_BYTES = NBUF * 2 * TT * CH * (int)sizeof(float); // 24 KB

__device__ float    g_A[1 << 18];
__device__ float    g_B[1 << 18];
__device__ unsigned g_flag[GRID];
__device__ unsigned g_cnt[GRID];

__device__ __forceinline__ void cpasync16(float* s, const float* g) {
    unsigned sa = (unsigned)__cvta_generic_to_shared(s);
    asm volatile("cp.async.cg.shared.global [%0], [%1], 16;\n"
                 :: "r"(sa), "l"(g) : "memory");
}

__device__ __forceinline__ void stcs(float* p, float v) {
    asm volatile("st.global.cs.f32 [%0], %1;\n" :: "l"(p), "f"(v) : "memory");
}

__device__ __forceinline__ unsigned ld_flag(const unsigned* p) {
    unsigned v;
    asm volatile("ld.global.cg.b32 %0, [%1];\n" : "=r"(v) : "l"(p) : "memory");
    return v;
}

__device__ __forceinline__ int read_dim(const void* p) {
    int i = *reinterpret_cast<const int*>(p);
    if (i >= 1 && i <= (1 << 20)) return i;
    float f = *reinterpret_cast<const float*>(p);
    int fi = (int)f;
    return (fi >= 1) ? fi : 1;
}

struct SegCtx {
    const float* kbase;
    const float* vbase;
    int segstart, segend, C, c0;
    bool valid, vec_ok;
};

__device__ __forceinline__ void load_tile(float* smem, int tid,
                                          const SegCtx& cx, int tile)
{
    const int buf = tile % NBUF;
    float* sk = smem + (size_t)buf * 2 * TT * CH;
    float* sv = sk + TT * CH;
    const int t0 = cx.segstart + tile * TT;
    if (cx.vec_ok) {
        #pragma unroll
        for (int j = 0; j < TT / 4; ++j) {
            const int q    = tid + j * CH;
            const int row  = q >> 5;
            const int col4 = (q & 31) * 4;
            int gt = t0 + row; if (gt >= cx.segend) gt = cx.segend - 1;
            const int gc = cx.c0 + col4;
            if (gc + 4 <= cx.C) {
                const long long go = (long long)gt * cx.C + gc;
                cpasync16(sk + row * CH + col4, cx.kbase + go);
                cpasync16(sv + row * CH + col4, cx.vbase + go);
            }
        }
    } else {
        for (int r = 0; r < TT; ++r) {
            int gt = t0 + r; if (gt >= cx.segend) gt = cx.segend - 1;
            if (cx.valid) {
                const long long go = (long long)gt * cx.C + (cx.c0 + tid);
                sk[r * CH + tid] = cx.kbase[go];
                sv[r * CH + tid] = cx.vbase[go];
            }
        }
    }
}

__device__ __forceinline__ void prefetch_prologue(float* smem, int tid,
                                                  const SegCtx& cx)
{
    const int ntiles = (cx.segend - cx.segstart + TT - 1) / TT;
    #pragma unroll
    for (int p = 0; p < NBUF - 1; ++p) {
        if (p < ntiles) load_tile(smem, tid, cx, p);
        asm volatile("cp.async.commit_group;\n" ::);
    }
}

template <bool EMIT, bool PRE>
__device__ __forceinline__ void scan_segment(
    float* smem, int tid, const SegCtx& cx,
    float* __restrict__ obase,            // out + b*T*C + c (EMIT only)
    float lam, float eu, float& A, float& Bs)
{
    const int ntiles = (cx.segend - cx.segstart + TT - 1) / TT;

    if (!PRE)
        prefetch_prologue(smem, tid, cx);

    for (int tile = 0; tile < ntiles; ++tile) {
        asm volatile("cp.async.wait_group %0;\n" :: "n"(NBUF - 2));
        __syncthreads();

        const int buf = tile % NBUF;
        const float* sk = smem + (size_t)buf * 2 * TT * CH + tid;
        const float* sv = sk + TT * CH;
        const int t0 = cx.segstart + tile * TT;
        const int jmax = min(TT, cx.segend - t0);

        #pragma unroll
        for (int j = 0; j < TT; ++j) {
            if (j < jmax) {
                const float kt = sk[j * CH];
                const float vt = sv[j * CH];
                const float ek = __expf(kt);
                if (EMIT) {
                    const float eku = eu * ek;
                    const float y = __fdividef(fmaf(eku, vt, A), Bs + eku);
                    if (cx.valid)
                        stcs(obase + (long long)(t0 + j) * cx.C, y);
                }
                A  = fmaf(lam, A,  ek * vt);
                Bs = fmaf(lam, Bs, ek);
            }
        }
        __syncthreads();

        const int nt = tile + NBUF - 1;
        if (nt < ntiles) load_tile(smem, tid, cx, nt);
        asm volatile("cp.async.commit_group;\n" ::);
    }
    asm volatile("cp.async.wait_group 0;\n" ::);
    __syncthreads();
}

__global__ __launch_bounds__(CH, 8)
void wkv_lookback_kernel(const void* __restrict__ seqlen_p,
                         const float* __restrict__ td,
                         const float* __restrict__ tf,
                         const float* __restrict__ kg,
                         const float* __restrict__ vg,
                         float* __restrict__ out,
                         int C, long long BTC)
{
    extern __shared__ float smem[];
    const int tid  = threadIdx.x;
    const int lane = tid & 31;

    const int T = read_dim(seqlen_p);
    const long long BT = BTC / C;
    const int B = (int)(BT / T);
    const int ctiles = (C + CH - 1) / CH;
    const int nrows  = B * ctiles;
    int S_eff = (int)(gridDim.x / nrows);      // one work item per block
    if (S_eff < 1) S_eff = 1;
    if (S_eff > S_MAX) S_eff = S_MAX;
    const int seglen = (T + S_eff - 1) / S_eff;
    const int nwork  = nrows * S_eff;
    const bool vec_ok = ((C & 3) == 0) &&
                        ((((uintptr_t)kg) & 15) == 0) &&
                        ((((uintptr_t)vg) & 15) == 0);

    // Ascending ids; waits only on strictly-lower ids -> forward progress
    // with any residency (CUB decoupled-lookback argument).
    for (int w = blockIdx.x; w < nwork; w += gridDim.x) {
        const int s     = w % S_eff;
        const int rowid = w / S_eff;
        const int b     = rowid / ctiles;
        const int c0    = (rowid % ctiles) * CH;
        const int c     = c0 + tid;
        const bool valid = (c < C);

        SegCtx cx;
        cx.kbase = kg + (long long)b * T * C;
        cx.vbase = vg + (long long)b * T * C;
        cx.segstart = min(s * seglen, T);
        cx.segend   = min(T, cx.segstart + seglen);
        cx.C = C; cx.c0 = c0; cx.valid = valid; cx.vec_ok = vec_ok;
        float* obase = out + (long long)b * T * C + c;

        if (cx.segstart >= cx.segend) continue;

        const float ew  = valid ? __expf(td[c]) : 0.f;  // e^{td}
        const float lam = __expf(-ew);                  // exp(-e^{td})
        const float eu  = valid ? __expf(tf[c]) : 0.f;

        float A = 0.f, Bs = 0.f;

        if (s == 0) {
            // Segment 0 needs no seed: single emitting sweep.
            scan_segment<true, false>(smem, tid, cx, obase, lam, eu, A, Bs);
            if (S_eff > 1) {
                const size_t st = (size_t)w * CH + tid;
                __stcg(&g_A[st], A);
                __stcg(&g_B[st], Bs);
                __threadfence();
                __syncthreads();
                if (tid == 0) atomicExch(&g_flag[w], 1u);
            }
            continue;
        }

        // ---- sweep 1: local scan from zero init ----
        scan_segment<false, false>(smem, tid, cx, nullptr, lam, 0.f, A, Bs);

        // ---- publish local state (only if someone will consume it) ----
        if (s < S_eff - 1) {
            const size_t st = (size_t)w * CH + tid;
            __stcg(&g_A[st], A);
            __stcg(&g_B[st], Bs);
            __threadfence();
            __syncthreads();
            if (tid == 0) atomicExch(&g_flag[w], 1u);
        }

        // ---- overlap: issue sweep-2's first tiles before the wait ----
        prefetch_prologue(smem, tid, cx);

        // ---- lookback: warp-level wait, then fold predecessor locals ----
        if (lane == 0) {
            for (int j = 0; j < s; ++j) {
                const unsigned* f = &g_flag[rowid * S_eff + j];
                while (ld_flag(f) == 0u) __nanosleep(64);
            }
        }
        __syncwarp();

        float sa = 0.f, sb = 0.f;
        #pragma unroll 4
        for (int j = 0; j < s; ++j) {
            int Lj = T - j * seglen;
            Lj = max(0, min(seglen, Lj));
            const float fdec = __expf(-(float)Lj * ew);  // lam^{L_j}
            const size_t st = (size_t)(rowid * S_eff + j) * CH + tid;
            sa = fmaf(fdec, sa, __ldcg(&g_A[st]));
            sb = fmaf(fdec, sb, __ldcg(&g_B[st]));
        }

        // ---- sweep 2: seeded re-scan, emit y ----
        A = sa; Bs = sb;
        scan_segment<true, true>(smem, tid, cx, obase, lam, eu, A, Bs);

        // ---- retire consumed flags (off critical path): last consumer of
        // slot j clears it so the next graph replay starts all-zero. ----
        __syncthreads();               // all threads done reading g_A/g_B
        if (tid == 0) {
            for (int j = 0; j < s; ++j) {
                const int wj = rowid * S_eff + j;
                const unsigned need = (unsigned)(S_eff - 1 - j);
                const unsigned got = atomicAdd(&g_cnt[wj], 1u) + 1u;
                if (got == need) {
                    g_cnt[wj] = 0u;
                    atomicExch(&g_flag[wj], 0u);
                }
            }
        }
    }
}

extern "C" void kernel_launch(void* const* d_in, const int* in_sizes, int n_in,
                              void* d_out, int out_size)
{
    // metadata order: batch_size, seq_len, embedding_dim, time_decay,
    //                 time_first, k, v
    const void*  seqlen_p = d_in[1];
    const float* td = (const float*)d_in[3];
    const float* tf = (const float*)d_in[4];
    const float* k  = (const float*)d_in[5];
    const float* v  = (const float*)d_in[6];
    float* out = (float*)d_out;

    const int C = in_sizes[3];
    const long long BTC = in_sizes[5];

    static bool attr_done = false;
    if (!attr_done) {
        cudaFuncSetAttribute(wkv_lookback_kernel,
                             cudaFuncAttributeMaxDynamicSharedMemorySize,
                             SMEM_BYTES);
        attr_done = true;
    }

    wkv_lookback_kernel<<<GRID, CH, SMEM_BYTES>>>(
        seqlen_p, td, tf, k, v, out, C, BTC);
}